// round 10
// baseline (speedup 1.0000x reference)
#include <cuda_runtime.h>
#include <cuda_fp16.h>
#include <cstdint>

// Problem constants (GAE_90589450207433)
#define N_NODES 100000
#define N_EDGES 3200000
#define IN_CH   256
#define HID     256
#define OUTC    128

#define SCAN_T    256
#define SCAN_NB   ((N_NODES + SCAN_T - 1) / SCAN_T)

#define CHUNK_A   50048                 // 391 * 128, first pipeline chunk
#define CHUNK_B   (N_NODES - CHUNK_A)

// ---------------- device scratch (no allocs allowed) ----------------
__device__ int   g_deg[N_NODES];
__device__ int   g_row_ptr[N_NODES + 1];
__device__ int   g_cursor[N_NODES];
__device__ float g_dinv[N_NODES];
__device__ int   g_csr_src[N_EDGES];
__device__ int   g_block_sums[SCAN_NB];
__device__ int   g_block_offs[SCAN_NB];
__device__ __align__(16) __half g_hp1h[(size_t)N_NODES * HID];   // fp16 xW1 (UNSCALED)
__device__ __align__(16) __half g_hp2h[(size_t)N_NODES * OUTC];  // fp16 dinv*(h2 W2)
__device__ __align__(16) __half g_h2h[(size_t)N_NODES * HID];    // relu(layer1 out), fp16

// ---------------- degree / norm ----------------
__global__ void init_deg_kernel() {
    int i = blockIdx.x * blockDim.x + threadIdx.x;
    if (i < N_NODES) g_deg[i] = 1;
}

__global__ void count_deg_kernel(const int* __restrict__ edge_index) {
    int t = blockIdx.x * blockDim.x + threadIdx.x;
    int e = t * 2;
    if (e + 1 < N_EDGES) {
        int2 d = *(const int2*)&edge_index[N_EDGES + e];
        if (d.x >= 0 && d.x < N_NODES) atomicAdd(&g_deg[d.x], 1);
        if (d.y >= 0 && d.y < N_NODES) atomicAdd(&g_deg[d.y], 1);
    } else if (e < N_EDGES) {
        int d = edge_index[N_EDGES + e];
        if (d >= 0 && d < N_NODES) atomicAdd(&g_deg[d], 1);
    }
}

__global__ void dinv_kernel() {
    int i = blockIdx.x * blockDim.x + threadIdx.x;
    if (i < N_NODES) g_dinv[i] = rsqrtf((float)g_deg[i]);
}

// ---------------- 3-phase multi-block exclusive scan of (deg-1) ----------------
__global__ __launch_bounds__(SCAN_T) void scan_partial_kernel() {
    __shared__ int warp_sums[SCAN_T / 32];
    int i = blockIdx.x * SCAN_T + threadIdx.x;
    int v = (i < N_NODES) ? (g_deg[i] - 1) : 0;
    int s = v;
#pragma unroll
    for (int off = 16; off > 0; off >>= 1) s += __shfl_down_sync(0xffffffffu, s, off);
    int lane = threadIdx.x & 31;
    int wid  = threadIdx.x >> 5;
    if (lane == 0) warp_sums[wid] = s;
    __syncthreads();
    if (wid == 0) {
        int t = (lane < SCAN_T / 32) ? warp_sums[lane] : 0;
#pragma unroll
        for (int off = 16; off > 0; off >>= 1) t += __shfl_down_sync(0xffffffffu, t, off);
        if (lane == 0) g_block_sums[blockIdx.x] = t;
    }
}

__global__ __launch_bounds__(1024) void scan_blocksums_kernel() {
    __shared__ int sh[1024];
    int tid = threadIdx.x;
    int v = (tid < SCAN_NB) ? g_block_sums[tid] : 0;
    sh[tid] = v;
    __syncthreads();
    for (int off = 1; off < 1024; off <<= 1) {
        int t = (tid >= off) ? sh[tid - off] : 0;
        __syncthreads();
        sh[tid] += t;
        __syncthreads();
    }
    if (tid < SCAN_NB) g_block_offs[tid] = sh[tid] - v;
    if (tid == 0) g_row_ptr[N_NODES] = N_EDGES;
}

__global__ __launch_bounds__(SCAN_T) void scan_scatter_kernel() {
    __shared__ int warp_incl[SCAN_T / 32];
    int i = blockIdx.x * SCAN_T + threadIdx.x;
    int v = (i < N_NODES) ? (g_deg[i] - 1) : 0;
    int lane = threadIdx.x & 31;
    int wid  = threadIdx.x >> 5;
    int incl = v;
#pragma unroll
    for (int off = 1; off < 32; off <<= 1) {
        int t = __shfl_up_sync(0xffffffffu, incl, off);
        if (lane >= off) incl += t;
    }
    if (lane == 31) warp_incl[wid] = incl;
    __syncthreads();
    if (wid == 0) {
        int t = (lane < SCAN_T / 32) ? warp_incl[lane] : 0;
#pragma unroll
        for (int off = 1; off < SCAN_T / 32; off <<= 1) {
            int u = __shfl_up_sync(0xffffffffu, t, off);
            if (lane >= off) t += u;
        }
        if (lane < SCAN_T / 32) warp_incl[lane] = t;
    }
    __syncthreads();
    int warp_off = (wid == 0) ? 0 : warp_incl[wid - 1];
    int excl = g_block_offs[blockIdx.x] + warp_off + (incl - v);
    if (i < N_NODES) {
        g_row_ptr[i] = excl;
        g_cursor[i]  = excl;
    }
}

__global__ void build_csr_kernel(const int* __restrict__ edge_index) {
    int t = blockIdx.x * blockDim.x + threadIdx.x;
    int e = t * 2;
    if (e + 1 < N_EDGES) {
        int2 s = *(const int2*)&edge_index[e];
        int2 d = *(const int2*)&edge_index[N_EDGES + e];
        if (d.x >= 0 && d.x < N_NODES && s.x >= 0 && s.x < N_NODES) {
            int pos = atomicAdd(&g_cursor[d.x], 1);
            g_csr_src[pos] = s.x;
        }
        if (d.y >= 0 && d.y < N_NODES && s.y >= 0 && s.y < N_NODES) {
            int pos = atomicAdd(&g_cursor[d.y], 1);
            g_csr_src[pos] = s.y;
        }
    } else if (e < N_EDGES) {
        int s = edge_index[e];
        int d = edge_index[N_EDGES + e];
        if (d >= 0 && d < N_NODES && s >= 0 && s < N_NODES) {
            int pos = atomicAdd(&g_cursor[d], 1);
            g_csr_src[pos] = s;
        }
    }
}

// ---------------- FP16 tensor-core GEMM ----------------
// MODE 0: C = fp16(x @ W1), NO dinv scale (applied later in SpMM1).
// MODE 1: C = fp16(dinv * (h2h @ W2)), chunked by row0/rows.
__device__ __forceinline__ void mma_f16(float* c, uint32_t a0, uint32_t a1,
                                        uint32_t a2, uint32_t a3,
                                        uint32_t b0, uint32_t b1) {
    asm volatile(
        "mma.sync.aligned.m16n8k16.row.col.f32.f16.f16.f32 "
        "{%0,%1,%2,%3}, {%4,%5,%6,%7}, {%8,%9}, {%0,%1,%2,%3};"
        : "+f"(c[0]), "+f"(c[1]), "+f"(c[2]), "+f"(c[3])
        : "r"(a0), "r"(a1), "r"(a2), "r"(a3), "r"(b0), "r"(b1));
}

#define APAD 4
#define BPAD 8
template <int MODE>
__global__ __launch_bounds__(256) void gemm_f16_kernel(
    const float* __restrict__ Aarg, const float* __restrict__ B,
    int row0, int rows, int K, int N)
{
    __half* __restrict__ C = (MODE == 0) ? g_hp1h : g_hp2h;
    const int Mend = row0 + rows;

    const int BM = 128, BN = 128, BK = 32;   // BK in halves
    __shared__ uint32_t As[BM][BK / 2 + APAD];
    __shared__ uint32_t Bs[BK / 2][BN + BPAD];

    int bm = row0 + blockIdx.x * BM;
    int bn = blockIdx.y * BN;
    int tid = threadIdx.x;
    int lane = tid & 31;
    int wid  = tid >> 5;
    int warp_m = wid & 1;
    int warp_n = wid >> 1;

    float acc[4][4][4];
#pragma unroll
    for (int mf = 0; mf < 4; mf++)
#pragma unroll
        for (int nf = 0; nf < 4; nf++)
#pragma unroll
            for (int c = 0; c < 4; c++) acc[mf][nf][c] = 0.f;

    int ar  = tid >> 3;
    int ac4 = (tid & 7) * 4;
    int bk2 = tid >> 5;
    int bcg = (tid & 31) * 4;

    for (int k0 = 0; k0 < K; k0 += BK) {
        if (MODE == 0) {
#pragma unroll
            for (int rr = 0; rr < 4; rr++) {
                int row = bm + ar + rr * 32;
                float4 v = make_float4(0.f, 0.f, 0.f, 0.f);
                if (row < Mend) v = *(const float4*)&Aarg[(size_t)row * K + k0 + ac4];
                __half2 h01 = __floats2half2_rn(v.x, v.y);
                __half2 h23 = __floats2half2_rn(v.z, v.w);
                As[ar + rr * 32][ac4 / 2]     = *(uint32_t*)&h01;
                As[ar + rr * 32][ac4 / 2 + 1] = *(uint32_t*)&h23;
            }
        } else {
#pragma unroll
            for (int rr = 0; rr < 4; rr++) {
                int row = bm + ar + rr * 32;
                uint2 v = make_uint2(0u, 0u);
                if (row < Mend) v = *(const uint2*)&g_h2h[(size_t)row * K + k0 + ac4];
                As[ar + rr * 32][ac4 / 2]     = v.x;
                As[ar + rr * 32][ac4 / 2 + 1] = v.y;
            }
        }
#pragma unroll
        for (int half = 0; half < 2; half++) {
            int k2 = bk2 + half * 8;
            int gk = k0 + 2 * k2;
            float4 r0 = *(const float4*)&B[(size_t)gk * N + bn + bcg];
            float4 r1 = *(const float4*)&B[(size_t)(gk + 1) * N + bn + bcg];
            __half2 p0 = __floats2half2_rn(r0.x, r1.x);
            __half2 p1 = __floats2half2_rn(r0.y, r1.y);
            __half2 p2 = __floats2half2_rn(r0.z, r1.z);
            __half2 p3 = __floats2half2_rn(r0.w, r1.w);
            Bs[k2][bcg + 0] = *(uint32_t*)&p0;
            Bs[k2][bcg + 1] = *(uint32_t*)&p1;
            Bs[k2][bcg + 2] = *(uint32_t*)&p2;
            Bs[k2][bcg + 3] = *(uint32_t*)&p3;
        }
        __syncthreads();

#pragma unroll
        for (int kk = 0; kk < 2; kk++) {
            uint32_t bf[4][2];
#pragma unroll
            for (int nf = 0; nf < 4; nf++) {
                int col = warp_n * 32 + nf * 8 + (lane >> 2);
                bf[nf][0] = Bs[kk * 8 + (lane & 3)][col];
                bf[nf][1] = Bs[kk * 8 + 4 + (lane & 3)][col];
            }
#pragma unroll
            for (int mf = 0; mf < 4; mf++) {
                int row = warp_m * 64 + mf * 16 + (lane >> 2);
                uint32_t a0 = As[row][kk * 8 + (lane & 3)];
                uint32_t a1 = As[row + 8][kk * 8 + (lane & 3)];
                uint32_t a2 = As[row][kk * 8 + 4 + (lane & 3)];
                uint32_t a3 = As[row + 8][kk * 8 + 4 + (lane & 3)];
#pragma unroll
                for (int nf = 0; nf < 4; nf++)
                    mma_f16(acc[mf][nf], a0, a1, a2, a3, bf[nf][0], bf[nf][1]);
            }
        }
        __syncthreads();
    }

#pragma unroll
    for (int mf = 0; mf < 4; mf++) {
        int r0 = bm + warp_m * 64 + mf * 16 + (lane >> 2);
        int r1 = r0 + 8;
        float d0 = 1.f, d1 = 1.f;
        if (MODE == 1) {
            d0 = (r0 < Mend) ? g_dinv[r0] : 0.f;
            d1 = (r1 < Mend) ? g_dinv[r1] : 0.f;
        }
#pragma unroll
        for (int nf = 0; nf < 4; nf++) {
            int cn = bn + warp_n * 32 + nf * 8 + (lane & 3) * 2;
            if (r0 < Mend) {
                __half2 h = __floats2half2_rn(acc[mf][nf][0] * d0, acc[mf][nf][1] * d0);
                *(__half2*)&C[(size_t)r0 * N + cn] = h;
            }
            if (r1 < Mend) {
                __half2 h = __floats2half2_rn(acc[mf][nf][2] * d1, acc[mf][nf][3] * d1);
                *(__half2*)&C[(size_t)r1 * N + cn] = h;
            }
        }
    }
}

// ---------------- SpMM aggregation over fp16 tables: one warp per dst row ----
// MODE 0: hp = g_hp1h (UNSCALED, 256 cols), per-edge dinv[s] scaling, out = g_h2h, relu.
// MODE 1: hp = g_hp2h (pre-scaled, 128 cols), out = arg (fp32).
template <int VEC, bool RELU, int MODE>
__global__ __launch_bounds__(256) void spmm_kernel(
    const float* __restrict__ bias, float* __restrict__ outarg,
    int row0, int rows)
{
    const uint32_t* __restrict__ hp =
        (const uint32_t*)((MODE == 0) ? (const __half*)g_hp1h : (const __half*)g_hp2h);

    const int ncol32 = VEC * 32;
    int warp = (blockIdx.x * blockDim.x + threadIdx.x) >> 5;
    int lane = threadIdx.x & 31;
    if (warp >= rows) return;
    int i = row0 + warp;

    float di = g_dinv[i];
    float acc[VEC * 2];
    {
        uint32_t v[VEC];
        const uint32_t* p = hp + (size_t)i * ncol32 + lane * VEC;
        if (VEC == 4) { uint4 u = *(const uint4*)p; v[0]=u.x; v[1]=u.y; v[2]=u.z; v[3]=u.w; }
        else          { uint2 u = *(const uint2*)p; v[0]=u.x; v[1]=u.y; }
        float sc = (MODE == 0) ? di : 1.f;   // self-loop scale
#pragma unroll
        for (int c = 0; c < VEC; c++) {
            float2 f = __half22float2(*(__half2*)&v[c]);
            acc[2*c] = sc * f.x; acc[2*c+1] = sc * f.y;
        }
    }

    int e = g_row_ptr[i];
    int end = g_row_ptr[i + 1];

    for (; e + 3 < end; e += 4) {
        int s0 = g_csr_src[e];
        int s1 = g_csr_src[e + 1];
        int s2 = g_csr_src[e + 2];
        int s3 = g_csr_src[e + 3];
        float ds0 = 1.f, ds1 = 1.f, ds2 = 1.f, ds3 = 1.f;
        if (MODE == 0) {
            ds0 = g_dinv[s0]; ds1 = g_dinv[s1]; ds2 = g_dinv[s2]; ds3 = g_dinv[s3];
        }
        uint32_t v0[VEC], v1[VEC], v2[VEC], v3[VEC];
        const uint32_t* p0 = hp + (size_t)s0 * ncol32 + lane * VEC;
        const uint32_t* p1 = hp + (size_t)s1 * ncol32 + lane * VEC;
        const uint32_t* p2 = hp + (size_t)s2 * ncol32 + lane * VEC;
        const uint32_t* p3 = hp + (size_t)s3 * ncol32 + lane * VEC;
        if (VEC == 4) {
            uint4 a = *(const uint4*)p0; v0[0]=a.x; v0[1]=a.y; v0[2]=a.z; v0[3]=a.w;
            uint4 b = *(const uint4*)p1; v1[0]=b.x; v1[1]=b.y; v1[2]=b.z; v1[3]=b.w;
            uint4 c = *(const uint4*)p2; v2[0]=c.x; v2[1]=c.y; v2[2]=c.z; v2[3]=c.w;
            uint4 d = *(const uint4*)p3; v3[0]=d.x; v3[1]=d.y; v3[2]=d.z; v3[3]=d.w;
        } else {
            uint2 a = *(const uint2*)p0; v0[0]=a.x; v0[1]=a.y;
            uint2 b = *(const uint2*)p1; v1[0]=b.x; v1[1]=b.y;
            uint2 c = *(const uint2*)p2; v2[0]=c.x; v2[1]=c.y;
            uint2 d = *(const uint2*)p3; v3[0]=d.x; v3[1]=d.y;
        }
#pragma unroll
        for (int c = 0; c < VEC; c++) {
            float2 f0 = __half22float2(*(__half2*)&v0[c]);
            float2 f1 = __half22float2(*(__half2*)&v1[c]);
            float2 f2 = __half22float2(*(__half2*)&v2[c]);
            float2 f3 = __half22float2(*(__half2*)&v3[c]);
            if (MODE == 0) {
                acc[2*c]   += ds0*f0.x + ds1*f1.x + ds2*f2.x + ds3*f3.x;
                acc[2*c+1] += ds0*f0.y + ds1*f1.y + ds2*f2.y + ds3*f3.y;
            } else {
                acc[2*c]   += (f0.x + f1.x) + (f2.x + f3.x);
                acc[2*c+1] += (f0.y + f1.y) + (f2.y + f3.y);
            }
        }
    }
    for (; e < end; e++) {
        int s0 = g_csr_src[e];
        float ds0 = (MODE == 0) ? g_dinv[s0] : 1.f;
        uint32_t v[VEC];
        const uint32_t* p = hp + (size_t)s0 * ncol32 + lane * VEC;
        if (VEC == 4) { uint4 u = *(const uint4*)p; v[0]=u.x; v[1]=u.y; v[2]=u.z; v[3]=u.w; }
        else          { uint2 u = *(const uint2*)p; v[0]=u.x; v[1]=u.y; }
#pragma unroll
        for (int c = 0; c < VEC; c++) {
            float2 f = __half22float2(*(__half2*)&v[c]);
            acc[2*c] += ds0 * f.x; acc[2*c+1] += ds0 * f.y;
        }
    }

    const float* bp = bias + lane * VEC * 2;
    float r[VEC * 2];
#pragma unroll
    for (int c = 0; c < VEC * 2; c += 4) {
        float4 bv = *(const float4*)&bp[c];
        r[c + 0] = fmaf(di, acc[c + 0], bv.x);
        r[c + 1] = fmaf(di, acc[c + 1], bv.y);
        r[c + 2] = fmaf(di, acc[c + 2], bv.z);
        r[c + 3] = fmaf(di, acc[c + 3], bv.w);
        if (RELU) {
            r[c + 0] = fmaxf(r[c + 0], 0.f); r[c + 1] = fmaxf(r[c + 1], 0.f);
            r[c + 2] = fmaxf(r[c + 2], 0.f); r[c + 3] = fmaxf(r[c + 3], 0.f);
        }
    }

    if (MODE == 0) {
        uint32_t* op = (uint32_t*)g_h2h + (size_t)i * ncol32 + lane * VEC;
        uint32_t w[VEC];
#pragma unroll
        for (int c = 0; c < VEC; c++) {
            __half2 h = __floats2half2_rn(r[2*c], r[2*c+1]);
            w[c] = *(uint32_t*)&h;
        }
        if (VEC == 4) *(uint4*)op = make_uint4(w[0], w[1], w[2], w[3]);
        else          *(uint2*)op = make_uint2(w[0], w[1]);
    } else {
        float* op = outarg + (size_t)i * ncol32 * 2 + lane * VEC * 2;
#pragma unroll
        for (int c = 0; c < VEC * 2; c += 4)
            *(float4*)&op[c] = make_float4(r[c], r[c+1], r[c+2], r[c+3]);
    }
}

// ---------------- launch ----------------
extern "C" void kernel_launch(void* const* d_in, const int* in_sizes, int n_in,
                              void* d_out, int out_size) {
    const float* x  = (const float*)d_in[0];
    const int*   ei = (const int*)d_in[1];
    const float* W1 = (const float*)d_in[2];
    const float* b1 = (const float*)d_in[3];
    const float* W2 = (const float*)d_in[4];
    const float* b2 = (const float*)d_in[5];
    float* out = (float*)d_out;

    const int T = 256;
    int nb_nodes = (N_NODES + T - 1) / T;
    int nb_edges2 = (N_EDGES / 2 + T - 1) / T;

    cudaStream_t s2;
    cudaEvent_t ev_root, ev_csr, ev_s1a, ev_g2a;
    cudaStreamCreateWithFlags(&s2, cudaStreamNonBlocking);
    cudaEventCreateWithFlags(&ev_root, cudaEventDisableTiming);
    cudaEventCreateWithFlags(&ev_csr, cudaEventDisableTiming);
    cudaEventCreateWithFlags(&ev_s1a, cudaEventDisableTiming);
    cudaEventCreateWithFlags(&ev_g2a, cudaEventDisableTiming);

    // Fork s2 FROM the capturing stream (required for stream-capture legality).
    cudaEventRecord(ev_root, 0);
    cudaStreamWaitEvent(s2, ev_root, 0);

    // ---- side stream: entire normalization + CSR pipeline ----
    init_deg_kernel<<<nb_nodes, T, 0, s2>>>();
    count_deg_kernel<<<nb_edges2, T, 0, s2>>>(ei);
    dinv_kernel<<<nb_nodes, T, 0, s2>>>();
    scan_partial_kernel<<<SCAN_NB, SCAN_T, 0, s2>>>();
    scan_blocksums_kernel<<<1, 1024, 0, s2>>>();
    scan_scatter_kernel<<<SCAN_NB, SCAN_T, 0, s2>>>();
    build_csr_kernel<<<nb_edges2, T, 0, s2>>>(ei);
    cudaEventRecord(ev_csr, s2);

    // ---- main stream: GEMM1 (dinv-free, starts at t=0) ----
    {
        dim3 grid((N_NODES + 127) / 128, HID / 128);
        gemm_f16_kernel<0><<<grid, 256>>>(x, W1, 0, N_NODES, IN_CH, HID);
    }

    // join: SpMM1 needs CSR + dinv + hp1h
    cudaStreamWaitEvent(0, ev_csr, 0);

    // ---- pipeline: SpMM1(A) -> [GEMM2(A) on s2 || SpMM1(B)] -> GEMM2(B) ----
    {
        int blocks = (CHUNK_A * 32 + T - 1) / T;
        spmm_kernel<4, true, 0><<<blocks, T>>>(b1, nullptr, 0, CHUNK_A);
    }
    cudaEventRecord(ev_s1a, 0);

    cudaStreamWaitEvent(s2, ev_s1a, 0);
    {
        dim3 grid((CHUNK_A + 127) / 128, OUTC / 128);
        gemm_f16_kernel<1><<<grid, 256, 0, s2>>>(nullptr, W2, 0, CHUNK_A, HID, OUTC);
    }
    cudaEventRecord(ev_g2a, s2);

    {
        int blocks = (CHUNK_B * 32 + T - 1) / T;
        spmm_kernel<4, true, 0><<<blocks, T>>>(b1, nullptr, CHUNK_A, CHUNK_B);
    }
    {
        dim3 grid((CHUNK_B + 127) / 128, OUTC / 128);
        gemm_f16_kernel<1><<<grid, 256>>>(nullptr, W2, CHUNK_A, CHUNK_B, HID, OUTC);
    }
    cudaStreamWaitEvent(0, ev_g2a, 0);

    // ---- final aggregation -> out ----
    {
        int blocks = (N_NODES * 32 + T - 1) / T;
        spmm_kernel<2, false, 1><<<blocks, T>>>(b2, out, 0, N_NODES);
    }
}

// round 11
// speedup vs baseline: 1.1232x; 1.1232x over previous
#include <cuda_runtime.h>
#include <cuda_fp16.h>
#include <cstdint>

// Problem constants (GAE_90589450207433)
#define N_NODES 100000
#define N_EDGES 3200000
#define IN_CH   256
#define HID     256
#define OUTC    128

#define SCAN_T    256
#define SCAN_NB   ((N_NODES + SCAN_T - 1) / SCAN_T)

// ---------------- device scratch (no allocs allowed) ----------------
// INVARIANT: g_deg is all-zero at kernel_launch entry (zero-init at load,
// re-zeroed at the end of every launch). deg counts EDGES only; self loop
// is accounted for via (deg+1) in dinv.
__device__ int   g_deg[N_NODES];
__device__ int   g_row_ptr[N_NODES + 1];
__device__ int   g_cursor[N_NODES];
__device__ float g_dinv[N_NODES];
__device__ int   g_csr_src[N_EDGES];
__device__ int   g_block_sums[SCAN_NB];
__device__ int   g_block_offs[SCAN_NB];
__device__ __align__(16) __half g_hp1h[(size_t)N_NODES * HID];   // fp16 dinv*(x W1)
__device__ __align__(16) __half g_hp2h[(size_t)N_NODES * OUTC];  // fp16 dinv*(h2 W2)
__device__ __align__(16) __half g_h2h[(size_t)N_NODES * HID];    // relu(layer1 out), fp16

// ---------------- degree / norm ----------------
__global__ void count_deg_kernel(const int* __restrict__ edge_index) {
    int t = blockIdx.x * blockDim.x + threadIdx.x;
    int e = t * 2;
    if (e + 1 < N_EDGES) {
        int2 d = *(const int2*)&edge_index[N_EDGES + e];
        if (d.x >= 0 && d.x < N_NODES) atomicAdd(&g_deg[d.x], 1);
        if (d.y >= 0 && d.y < N_NODES) atomicAdd(&g_deg[d.y], 1);
    } else if (e < N_EDGES) {
        int d = edge_index[N_EDGES + e];
        if (d >= 0 && d < N_NODES) atomicAdd(&g_deg[d], 1);
    }
}

__global__ void dinv_kernel() {
    int i = blockIdx.x * blockDim.x + threadIdx.x;
    if (i < N_NODES) g_dinv[i] = rsqrtf((float)(g_deg[i] + 1));  // +1 = self loop
}

__global__ void zero_deg_kernel() {
    int i = blockIdx.x * blockDim.x + threadIdx.x;
    if (i < N_NODES) g_deg[i] = 0;   // restore entry invariant for next replay
}

// ---------------- 3-phase multi-block exclusive scan of deg ----------------
__global__ __launch_bounds__(SCAN_T) void scan_partial_kernel() {
    __shared__ int warp_sums[SCAN_T / 32];
    int i = blockIdx.x * SCAN_T + threadIdx.x;
    int v = (i < N_NODES) ? g_deg[i] : 0;
    int s = v;
#pragma unroll
    for (int off = 16; off > 0; off >>= 1) s += __shfl_down_sync(0xffffffffu, s, off);
    int lane = threadIdx.x & 31;
    int wid  = threadIdx.x >> 5;
    if (lane == 0) warp_sums[wid] = s;
    __syncthreads();
    if (wid == 0) {
        int t = (lane < SCAN_T / 32) ? warp_sums[lane] : 0;
#pragma unroll
        for (int off = 16; off > 0; off >>= 1) t += __shfl_down_sync(0xffffffffu, t, off);
        if (lane == 0) g_block_sums[blockIdx.x] = t;
    }
}

__global__ __launch_bounds__(1024) void scan_blocksums_kernel() {
    __shared__ int sh[1024];
    int tid = threadIdx.x;
    int v = (tid < SCAN_NB) ? g_block_sums[tid] : 0;
    sh[tid] = v;
    __syncthreads();
    for (int off = 1; off < 1024; off <<= 1) {
        int t = (tid >= off) ? sh[tid - off] : 0;
        __syncthreads();
        sh[tid] += t;
        __syncthreads();
    }
    if (tid < SCAN_NB) g_block_offs[tid] = sh[tid] - v;
    if (tid == 0) g_row_ptr[N_NODES] = N_EDGES;
}

__global__ __launch_bounds__(SCAN_T) void scan_scatter_kernel() {
    __shared__ int warp_incl[SCAN_T / 32];
    int i = blockIdx.x * SCAN_T + threadIdx.x;
    int v = (i < N_NODES) ? g_deg[i] : 0;
    int lane = threadIdx.x & 31;
    int wid  = threadIdx.x >> 5;
    int incl = v;
#pragma unroll
    for (int off = 1; off < 32; off <<= 1) {
        int t = __shfl_up_sync(0xffffffffu, incl, off);
        if (lane >= off) incl += t;
    }
    if (lane == 31) warp_incl[wid] = incl;
    __syncthreads();
    if (wid == 0) {
        int t = (lane < SCAN_T / 32) ? warp_incl[lane] : 0;
#pragma unroll
        for (int off = 1; off < SCAN_T / 32; off <<= 1) {
            int u = __shfl_up_sync(0xffffffffu, t, off);
            if (lane >= off) t += u;
        }
        if (lane < SCAN_T / 32) warp_incl[lane] = t;
    }
    __syncthreads();
    int warp_off = (wid == 0) ? 0 : warp_incl[wid - 1];
    int excl = g_block_offs[blockIdx.x] + warp_off + (incl - v);
    if (i < N_NODES) {
        g_row_ptr[i] = excl;
        g_cursor[i]  = excl;
    }
}

__global__ void build_csr_kernel(const int* __restrict__ edge_index) {
    int t = blockIdx.x * blockDim.x + threadIdx.x;
    int e = t * 2;
    if (e + 1 < N_EDGES) {
        int2 s = *(const int2*)&edge_index[e];
        int2 d = *(const int2*)&edge_index[N_EDGES + e];
        if (d.x >= 0 && d.x < N_NODES && s.x >= 0 && s.x < N_NODES) {
            int pos = atomicAdd(&g_cursor[d.x], 1);
            g_csr_src[pos] = s.x;
        }
        if (d.y >= 0 && d.y < N_NODES && s.y >= 0 && s.y < N_NODES) {
            int pos = atomicAdd(&g_cursor[d.y], 1);
            g_csr_src[pos] = s.y;
        }
    } else if (e < N_EDGES) {
        int s = edge_index[e];
        int d = edge_index[N_EDGES + e];
        if (d >= 0 && d < N_NODES && s >= 0 && s < N_NODES) {
            int pos = atomicAdd(&g_cursor[d], 1);
            g_csr_src[pos] = s;
        }
    }
}

// ---------------- FP16 tensor-core GEMM: Ch[row] = fp16(dinv[row]*(A@B)[row]) ----
__device__ __forceinline__ void mma_f16(float* c, uint32_t a0, uint32_t a1,
                                        uint32_t a2, uint32_t a3,
                                        uint32_t b0, uint32_t b1) {
    asm volatile(
        "mma.sync.aligned.m16n8k16.row.col.f32.f16.f16.f32 "
        "{%0,%1,%2,%3}, {%4,%5,%6,%7}, {%8,%9}, {%0,%1,%2,%3};"
        : "+f"(c[0]), "+f"(c[1]), "+f"(c[2]), "+f"(c[3])
        : "r"(a0), "r"(a1), "r"(a2), "r"(a3), "r"(b0), "r"(b1));
}

#define APAD 4
#define BPAD 8
template <int MODE>
__global__ __launch_bounds__(256) void gemm_f16_kernel(
    const float* __restrict__ Aarg, const float* __restrict__ B,
    int M, int K, int N)
{
    __half* __restrict__ C = (MODE == 0) ? g_hp1h : g_hp2h;

    const int BM = 128, BN = 128, BK = 32;   // BK in halves
    __shared__ uint32_t As[BM][BK / 2 + APAD];
    __shared__ uint32_t Bs[BK / 2][BN + BPAD];

    int bm = blockIdx.x * BM;
    int bn = blockIdx.y * BN;
    int tid = threadIdx.x;
    int lane = tid & 31;
    int wid  = tid >> 5;
    int warp_m = wid & 1;
    int warp_n = wid >> 1;

    float acc[4][4][4];
#pragma unroll
    for (int mf = 0; mf < 4; mf++)
#pragma unroll
        for (int nf = 0; nf < 4; nf++)
#pragma unroll
            for (int c = 0; c < 4; c++) acc[mf][nf][c] = 0.f;

    int ar  = tid >> 3;
    int ac4 = (tid & 7) * 4;
    int bk2 = tid >> 5;
    int bcg = (tid & 31) * 4;

    for (int k0 = 0; k0 < K; k0 += BK) {
        if (MODE == 0) {
#pragma unroll
            for (int rr = 0; rr < 4; rr++) {
                int row = bm + ar + rr * 32;
                float4 v = make_float4(0.f, 0.f, 0.f, 0.f);
                if (row < M) v = *(const float4*)&Aarg[(size_t)row * K + k0 + ac4];
                __half2 h01 = __floats2half2_rn(v.x, v.y);
                __half2 h23 = __floats2half2_rn(v.z, v.w);
                As[ar + rr * 32][ac4 / 2]     = *(uint32_t*)&h01;
                As[ar + rr * 32][ac4 / 2 + 1] = *(uint32_t*)&h23;
            }
        } else {
#pragma unroll
            for (int rr = 0; rr < 4; rr++) {
                int row = bm + ar + rr * 32;
                uint2 v = make_uint2(0u, 0u);
                if (row < M) v = *(const uint2*)&g_h2h[(size_t)row * K + k0 + ac4];
                As[ar + rr * 32][ac4 / 2]     = v.x;
                As[ar + rr * 32][ac4 / 2 + 1] = v.y;
            }
        }
#pragma unroll
        for (int half = 0; half < 2; half++) {
            int k2 = bk2 + half * 8;
            int gk = k0 + 2 * k2;
            float4 r0 = *(const float4*)&B[(size_t)gk * N + bn + bcg];
            float4 r1 = *(const float4*)&B[(size_t)(gk + 1) * N + bn + bcg];
            __half2 p0 = __floats2half2_rn(r0.x, r1.x);
            __half2 p1 = __floats2half2_rn(r0.y, r1.y);
            __half2 p2 = __floats2half2_rn(r0.z, r1.z);
            __half2 p3 = __floats2half2_rn(r0.w, r1.w);
            Bs[k2][bcg + 0] = *(uint32_t*)&p0;
            Bs[k2][bcg + 1] = *(uint32_t*)&p1;
            Bs[k2][bcg + 2] = *(uint32_t*)&p2;
            Bs[k2][bcg + 3] = *(uint32_t*)&p3;
        }
        __syncthreads();

#pragma unroll
        for (int kk = 0; kk < 2; kk++) {
            uint32_t bf[4][2];
#pragma unroll
            for (int nf = 0; nf < 4; nf++) {
                int col = warp_n * 32 + nf * 8 + (lane >> 2);
                bf[nf][0] = Bs[kk * 8 + (lane & 3)][col];
                bf[nf][1] = Bs[kk * 8 + 4 + (lane & 3)][col];
            }
#pragma unroll
            for (int mf = 0; mf < 4; mf++) {
                int row = warp_m * 64 + mf * 16 + (lane >> 2);
                uint32_t a0 = As[row][kk * 8 + (lane & 3)];
                uint32_t a1 = As[row + 8][kk * 8 + (lane & 3)];
                uint32_t a2 = As[row][kk * 8 + 4 + (lane & 3)];
                uint32_t a3 = As[row + 8][kk * 8 + 4 + (lane & 3)];
#pragma unroll
                for (int nf = 0; nf < 4; nf++)
                    mma_f16(acc[mf][nf], a0, a1, a2, a3, bf[nf][0], bf[nf][1]);
            }
        }
        __syncthreads();
    }

#pragma unroll
    for (int mf = 0; mf < 4; mf++) {
        int r0 = bm + warp_m * 64 + mf * 16 + (lane >> 2);
        int r1 = r0 + 8;
        float d0 = (r0 < M) ? g_dinv[r0] : 0.f;
        float d1 = (r1 < M) ? g_dinv[r1] : 0.f;
#pragma unroll
        for (int nf = 0; nf < 4; nf++) {
            int cn = bn + warp_n * 32 + nf * 8 + (lane & 3) * 2;
            if (r0 < M) {
                __half2 h = __floats2half2_rn(acc[mf][nf][0] * d0, acc[mf][nf][1] * d0);
                *(__half2*)&C[(size_t)r0 * N + cn] = h;
            }
            if (r1 < M) {
                __half2 h = __floats2half2_rn(acc[mf][nf][2] * d1, acc[mf][nf][3] * d1);
                *(__half2*)&C[(size_t)r1 * N + cn] = h;
            }
        }
    }
}

// ---------------- SpMM aggregation over fp16 tables: one warp per dst row ----
// out[i] = act( dinv[i] * (sum_{src in N(i)} hp[src] + hp[i]) + bias )
// MODE 0: hp = g_hp1h (256 cols), out = g_h2h (fp16), relu.
// MODE 1: hp = g_hp2h (128 cols), out = arg (fp32).
template <int VEC, bool RELU, int MODE>
__global__ __launch_bounds__(256) void spmm_kernel(
    const float* __restrict__ bias, float* __restrict__ outarg)
{
    const uint32_t* __restrict__ hp =
        (const uint32_t*)((MODE == 0) ? (const __half*)g_hp1h : (const __half*)g_hp2h);

    const int ncol32 = VEC * 32;
    int warp = (blockIdx.x * blockDim.x + threadIdx.x) >> 5;
    int lane = threadIdx.x & 31;
    if (warp >= N_NODES) return;
    int i = warp;

    float acc[VEC * 2];
    {
        uint32_t v[VEC];
        const uint32_t* p = hp + (size_t)i * ncol32 + lane * VEC;
        if (VEC == 4) { uint4 u = *(const uint4*)p; v[0]=u.x; v[1]=u.y; v[2]=u.z; v[3]=u.w; }
        else          { uint2 u = *(const uint2*)p; v[0]=u.x; v[1]=u.y; }
#pragma unroll
        for (int c = 0; c < VEC; c++) {
            float2 f = __half22float2(*(__half2*)&v[c]);
            acc[2*c] = f.x; acc[2*c+1] = f.y;
        }
    }

    int e = g_row_ptr[i];
    int end = g_row_ptr[i + 1];

    for (; e + 3 < end; e += 4) {
        int s0 = g_csr_src[e];
        int s1 = g_csr_src[e + 1];
        int s2 = g_csr_src[e + 2];
        int s3 = g_csr_src[e + 3];
        uint32_t v0[VEC], v1[VEC], v2[VEC], v3[VEC];
        const uint32_t* p0 = hp + (size_t)s0 * ncol32 + lane * VEC;
        const uint32_t* p1 = hp + (size_t)s1 * ncol32 + lane * VEC;
        const uint32_t* p2 = hp + (size_t)s2 * ncol32 + lane * VEC;
        const uint32_t* p3 = hp + (size_t)s3 * ncol32 + lane * VEC;
        if (VEC == 4) {
            uint4 a = *(const uint4*)p0; v0[0]=a.x; v0[1]=a.y; v0[2]=a.z; v0[3]=a.w;
            uint4 b = *(const uint4*)p1; v1[0]=b.x; v1[1]=b.y; v1[2]=b.z; v1[3]=b.w;
            uint4 c = *(const uint4*)p2; v2[0]=c.x; v2[1]=c.y; v2[2]=c.z; v2[3]=c.w;
            uint4 d = *(const uint4*)p3; v3[0]=d.x; v3[1]=d.y; v3[2]=d.z; v3[3]=d.w;
        } else {
            uint2 a = *(const uint2*)p0; v0[0]=a.x; v0[1]=a.y;
            uint2 b = *(const uint2*)p1; v1[0]=b.x; v1[1]=b.y;
            uint2 c = *(const uint2*)p2; v2[0]=c.x; v2[1]=c.y;
            uint2 d = *(const uint2*)p3; v3[0]=d.x; v3[1]=d.y;
        }
#pragma unroll
        for (int c = 0; c < VEC; c++) {
            float2 f0 = __half22float2(*(__half2*)&v0[c]);
            float2 f1 = __half22float2(*(__half2*)&v1[c]);
            float2 f2 = __half22float2(*(__half2*)&v2[c]);
            float2 f3 = __half22float2(*(__half2*)&v3[c]);
            acc[2*c]   += (f0.x + f1.x) + (f2.x + f3.x);
            acc[2*c+1] += (f0.y + f1.y) + (f2.y + f3.y);
        }
    }
    for (; e < end; e++) {
        int s0 = g_csr_src[e];
        uint32_t v[VEC];
        const uint32_t* p = hp + (size_t)s0 * ncol32 + lane * VEC;
        if (VEC == 4) { uint4 u = *(const uint4*)p; v[0]=u.x; v[1]=u.y; v[2]=u.z; v[3]=u.w; }
        else          { uint2 u = *(const uint2*)p; v[0]=u.x; v[1]=u.y; }
#pragma unroll
        for (int c = 0; c < VEC; c++) {
            float2 f = __half22float2(*(__half2*)&v[c]);
            acc[2*c] += f.x; acc[2*c+1] += f.y;
        }
    }

    float di = g_dinv[i];
    const float* bp = bias + lane * VEC * 2;
    float r[VEC * 2];
#pragma unroll
    for (int c = 0; c < VEC * 2; c += 4) {
        float4 bv = *(const float4*)&bp[c];
        r[c + 0] = fmaf(di, acc[c + 0], bv.x);
        r[c + 1] = fmaf(di, acc[c + 1], bv.y);
        r[c + 2] = fmaf(di, acc[c + 2], bv.z);
        r[c + 3] = fmaf(di, acc[c + 3], bv.w);
        if (RELU) {
            r[c + 0] = fmaxf(r[c + 0], 0.f); r[c + 1] = fmaxf(r[c + 1], 0.f);
            r[c + 2] = fmaxf(r[c + 2], 0.f); r[c + 3] = fmaxf(r[c + 3], 0.f);
        }
    }

    if (MODE == 0) {
        uint32_t* op = (uint32_t*)g_h2h + (size_t)i * ncol32 + lane * VEC;
        uint32_t w[VEC];
#pragma unroll
        for (int c = 0; c < VEC; c++) {
            __half2 h = __floats2half2_rn(r[2*c], r[2*c+1]);
            w[c] = *(uint32_t*)&h;
        }
        if (VEC == 4) *(uint4*)op = make_uint4(w[0], w[1], w[2], w[3]);
        else          *(uint2*)op = make_uint2(w[0], w[1]);
    } else {
        float* op = outarg + (size_t)i * ncol32 * 2 + lane * VEC * 2;
#pragma unroll
        for (int c = 0; c < VEC * 2; c += 4)
            *(float4*)&op[c] = make_float4(r[c], r[c+1], r[c+2], r[c+3]);
    }
}

// ---------------- launch ----------------
extern "C" void kernel_launch(void* const* d_in, const int* in_sizes, int n_in,
                              void* d_out, int out_size) {
    const float* x  = (const float*)d_in[0];
    const int*   ei = (const int*)d_in[1];
    const float* W1 = (const float*)d_in[2];
    const float* b1 = (const float*)d_in[3];
    const float* W2 = (const float*)d_in[4];
    const float* b2 = (const float*)d_in[5];
    float* out = (float*)d_out;

    const int T = 256;
    int nb_nodes = (N_NODES + T - 1) / T;
    int nb_edges2 = (N_EDGES / 2 + T - 1) / T;

    cudaStream_t s2;
    cudaEvent_t ev_deg, ev_csr, ev_zero;
    cudaStreamCreateWithFlags(&s2, cudaStreamNonBlocking);
    cudaEventCreateWithFlags(&ev_deg, cudaEventDisableTiming);
    cudaEventCreateWithFlags(&ev_csr, cudaEventDisableTiming);
    cudaEventCreateWithFlags(&ev_zero, cudaEventDisableTiming);

    // main stream: degree + dinv (deg is zero on entry; no init kernel)
    count_deg_kernel<<<nb_edges2, T>>>(ei);
    dinv_kernel<<<nb_nodes, T>>>();
    cudaEventRecord(ev_deg, 0);

    // side stream (forked from capture stream via ev_deg): scan + CSR build,
    // then restore the deg==0 entry invariant (overlapped under later work).
    cudaStreamWaitEvent(s2, ev_deg, 0);
    scan_partial_kernel<<<SCAN_NB, SCAN_T, 0, s2>>>();
    scan_blocksums_kernel<<<1, 1024, 0, s2>>>();
    scan_scatter_kernel<<<SCAN_NB, SCAN_T, 0, s2>>>();
    build_csr_kernel<<<nb_edges2, T, 0, s2>>>(ei);
    cudaEventRecord(ev_csr, s2);
    zero_deg_kernel<<<nb_nodes, T, 0, s2>>>();
    cudaEventRecord(ev_zero, s2);

    // main stream: GEMM1 in parallel with CSR build (needs only dinv)
    {
        dim3 grid((N_NODES + 127) / 128, HID / 128);
        gemm_f16_kernel<0><<<grid, 256>>>(x, W1, N_NODES, IN_CH, HID);
    }

    // join: SpMM1 needs CSR + hp1h
    cudaStreamWaitEvent(0, ev_csr, 0);
    {
        int blocks = (N_NODES * 32 + T - 1) / T;
        spmm_kernel<4, true, 0><<<blocks, T>>>(b1, nullptr);
    }
    {
        dim3 grid((N_NODES + 127) / 128, OUTC / 128);
        gemm_f16_kernel<1><<<grid, 256>>>(nullptr, W2, N_NODES, HID, OUTC);
    }
    {
        int blocks = (N_NODES * 32 + T - 1) / T;
        spmm_kernel<2, false, 1><<<blocks, T>>>(b2, out);
    }
    // join side-stream cleanup back into the capture stream before return
    cudaStreamWaitEvent(0, ev_zero, 0);
}

// round 12
// speedup vs baseline: 1.1381x; 1.0133x over previous
#include <cuda_runtime.h>
#include <cuda_fp16.h>
#include <cstdint>

// Problem constants (GAE_90589450207433)
#define N_NODES 100000
#define N_EDGES 3200000
#define IN_CH   256
#define HID     256
#define OUTC    128

#define SCAN_T    256
#define SCAN_NB   ((N_NODES + SCAN_T - 1) / SCAN_T)

// ---------------- device scratch (no allocs allowed) ----------------
// INVARIANT: g_deg is all-zero at kernel_launch entry (zero-init at load,
// re-zeroed at the end of every launch). deg counts EDGES only; self loop
// is accounted for via (deg+1) in dinv.
__device__ int   g_deg[N_NODES];
__device__ int   g_row_ptr[N_NODES + 1];
__device__ int   g_cursor[N_NODES];
__device__ float g_dinv[N_NODES];
__device__ int   g_csr_src[N_EDGES];
__device__ int   g_block_sums[SCAN_NB];
__device__ int   g_block_offs[SCAN_NB];
__device__ __align__(16) __half g_hp1h[(size_t)N_NODES * HID];   // fp16 dinv*(x W1)
__device__ __align__(16) __half g_hp2h[(size_t)N_NODES * OUTC];  // fp16 dinv*(h2 W2)
__device__ __align__(16) __half g_h2h[(size_t)N_NODES * HID];    // relu(layer1 out), fp16

// ---------------- degree / norm ----------------
__global__ void count_deg_kernel(const int* __restrict__ edge_index) {
    int t = blockIdx.x * blockDim.x + threadIdx.x;
    int e = t * 2;
    if (e + 1 < N_EDGES) {
        int2 d = *(const int2*)&edge_index[N_EDGES + e];
        if (d.x >= 0 && d.x < N_NODES) atomicAdd(&g_deg[d.x], 1);
        if (d.y >= 0 && d.y < N_NODES) atomicAdd(&g_deg[d.y], 1);
    } else if (e < N_EDGES) {
        int d = edge_index[N_EDGES + e];
        if (d >= 0 && d < N_NODES) atomicAdd(&g_deg[d], 1);
    }
}

__global__ void dinv_kernel() {
    int i = blockIdx.x * blockDim.x + threadIdx.x;
    if (i < N_NODES) g_dinv[i] = rsqrtf((float)(g_deg[i] + 1));  // +1 = self loop
}

__global__ void zero_deg_kernel() {
    int i = blockIdx.x * blockDim.x + threadIdx.x;
    if (i < N_NODES) g_deg[i] = 0;   // restore entry invariant for next replay
}

// ---------------- 3-phase multi-block exclusive scan of deg ----------------
__global__ __launch_bounds__(SCAN_T) void scan_partial_kernel() {
    __shared__ int warp_sums[SCAN_T / 32];
    int i = blockIdx.x * SCAN_T + threadIdx.x;
    int v = (i < N_NODES) ? g_deg[i] : 0;
    int s = v;
#pragma unroll
    for (int off = 16; off > 0; off >>= 1) s += __shfl_down_sync(0xffffffffu, s, off);
    int lane = threadIdx.x & 31;
    int wid  = threadIdx.x >> 5;
    if (lane == 0) warp_sums[wid] = s;
    __syncthreads();
    if (wid == 0) {
        int t = (lane < SCAN_T / 32) ? warp_sums[lane] : 0;
#pragma unroll
        for (int off = 16; off > 0; off >>= 1) t += __shfl_down_sync(0xffffffffu, t, off);
        if (lane == 0) g_block_sums[blockIdx.x] = t;
    }
}

__global__ __launch_bounds__(1024) void scan_blocksums_kernel() {
    __shared__ int sh[1024];
    int tid = threadIdx.x;
    int v = (tid < SCAN_NB) ? g_block_sums[tid] : 0;
    sh[tid] = v;
    __syncthreads();
    for (int off = 1; off < 1024; off <<= 1) {
        int t = (tid >= off) ? sh[tid - off] : 0;
        __syncthreads();
        sh[tid] += t;
        __syncthreads();
    }
    if (tid < SCAN_NB) g_block_offs[tid] = sh[tid] - v;
    if (tid == 0) g_row_ptr[N_NODES] = N_EDGES;
}

__global__ __launch_bounds__(SCAN_T) void scan_scatter_kernel() {
    __shared__ int warp_incl[SCAN_T / 32];
    int i = blockIdx.x * SCAN_T + threadIdx.x;
    int v = (i < N_NODES) ? g_deg[i] : 0;
    int lane = threadIdx.x & 31;
    int wid  = threadIdx.x >> 5;
    int incl = v;
#pragma unroll
    for (int off = 1; off < 32; off <<= 1) {
        int t = __shfl_up_sync(0xffffffffu, incl, off);
        if (lane >= off) incl += t;
    }
    if (lane == 31) warp_incl[wid] = incl;
    __syncthreads();
    if (wid == 0) {
        int t = (lane < SCAN_T / 32) ? warp_incl[lane] : 0;
#pragma unroll
        for (int off = 1; off < SCAN_T / 32; off <<= 1) {
            int u = __shfl_up_sync(0xffffffffu, t, off);
            if (lane >= off) t += u;
        }
        if (lane < SCAN_T / 32) warp_incl[lane] = t;
    }
    __syncthreads();
    int warp_off = (wid == 0) ? 0 : warp_incl[wid - 1];
    int excl = g_block_offs[blockIdx.x] + warp_off + (incl - v);
    if (i < N_NODES) {
        g_row_ptr[i] = excl;
        g_cursor[i]  = excl;
    }
}

__global__ void build_csr_kernel(const int* __restrict__ edge_index) {
    int t = blockIdx.x * blockDim.x + threadIdx.x;
    int e = t * 2;
    if (e + 1 < N_EDGES) {
        int2 s = *(const int2*)&edge_index[e];
        int2 d = *(const int2*)&edge_index[N_EDGES + e];
        if (d.x >= 0 && d.x < N_NODES && s.x >= 0 && s.x < N_NODES) {
            int pos = atomicAdd(&g_cursor[d.x], 1);
            g_csr_src[pos] = s.x;
        }
        if (d.y >= 0 && d.y < N_NODES && s.y >= 0 && s.y < N_NODES) {
            int pos = atomicAdd(&g_cursor[d.y], 1);
            g_csr_src[pos] = s.y;
        }
    } else if (e < N_EDGES) {
        int s = edge_index[e];
        int d = edge_index[N_EDGES + e];
        if (d >= 0 && d < N_NODES && s >= 0 && s < N_NODES) {
            int pos = atomicAdd(&g_cursor[d], 1);
            g_csr_src[pos] = s;
        }
    }
}

// ---------------- FP16 tensor-core GEMM (software-pipelined) ----------------
// Ch[row] = fp16(dinv[row] * (A@B)[row])
__device__ __forceinline__ void mma_f16(float* c, uint32_t a0, uint32_t a1,
                                        uint32_t a2, uint32_t a3,
                                        uint32_t b0, uint32_t b1) {
    asm volatile(
        "mma.sync.aligned.m16n8k16.row.col.f32.f16.f16.f32 "
        "{%0,%1,%2,%3}, {%4,%5,%6,%7}, {%8,%9}, {%0,%1,%2,%3};"
        : "+f"(c[0]), "+f"(c[1]), "+f"(c[2]), "+f"(c[3])
        : "r"(a0), "r"(a1), "r"(a2), "r"(a3), "r"(b0), "r"(b1));
}

#define APAD 4
#define BPAD 8
template <int MODE>
__global__ __launch_bounds__(256) void gemm_f16_kernel(
    const float* __restrict__ Aarg, const float* __restrict__ B,
    int M, int K, int N)
{
    __half* __restrict__ C = (MODE == 0) ? g_hp1h : g_hp2h;

    const int BM = 128, BN = 128, BK = 32;   // BK in halves
    __shared__ uint32_t As[BM][BK / 2 + APAD];
    __shared__ uint32_t Bs[BK / 2][BN + BPAD];

    int bm = blockIdx.x * BM;
    int bn = blockIdx.y * BN;
    int tid = threadIdx.x;
    int lane = tid & 31;
    int wid  = tid >> 5;
    int warp_m = wid & 1;
    int warp_n = wid >> 1;

    float acc[4][4][4];
#pragma unroll
    for (int mf = 0; mf < 4; mf++)
#pragma unroll
        for (int nf = 0; nf < 4; nf++)
#pragma unroll
            for (int c = 0; c < 4; c++) acc[mf][nf][c] = 0.f;

    int ar  = tid >> 3;
    int ac4 = (tid & 7) * 4;
    int bk2 = tid >> 5;
    int bcg = (tid & 31) * 4;

    // register staging for prefetched tile
    uint2  a_reg[4];
    float4 b_reg0[2], b_reg1[2];

    // ---- prologue: fetch tile k0=0 into registers ----
    auto fetch_tile = [&](int k0) {
#pragma unroll
        for (int rr = 0; rr < 4; rr++) {
            int row = bm + ar + rr * 32;
            if (MODE == 0) {
                float4 v = make_float4(0.f, 0.f, 0.f, 0.f);
                if (row < M) v = *(const float4*)&Aarg[(size_t)row * K + k0 + ac4];
                __half2 h01 = __floats2half2_rn(v.x, v.y);
                __half2 h23 = __floats2half2_rn(v.z, v.w);
                a_reg[rr].x = *(uint32_t*)&h01;
                a_reg[rr].y = *(uint32_t*)&h23;
            } else {
                uint2 v = make_uint2(0u, 0u);
                if (row < M) v = *(const uint2*)&g_h2h[(size_t)row * K + k0 + ac4];
                a_reg[rr] = v;
            }
        }
#pragma unroll
        for (int half = 0; half < 2; half++) {
            int k2 = bk2 + half * 8;
            int gk = k0 + 2 * k2;
            b_reg0[half] = *(const float4*)&B[(size_t)gk * N + bn + bcg];
            b_reg1[half] = *(const float4*)&B[(size_t)(gk + 1) * N + bn + bcg];
        }
    };
    auto store_tile = [&]() {
#pragma unroll
        for (int rr = 0; rr < 4; rr++) {
            As[ar + rr * 32][ac4 / 2]     = a_reg[rr].x;
            As[ar + rr * 32][ac4 / 2 + 1] = a_reg[rr].y;
        }
#pragma unroll
        for (int half = 0; half < 2; half++) {
            int k2 = bk2 + half * 8;
            __half2 p0 = __floats2half2_rn(b_reg0[half].x, b_reg1[half].x);
            __half2 p1 = __floats2half2_rn(b_reg0[half].y, b_reg1[half].y);
            __half2 p2 = __floats2half2_rn(b_reg0[half].z, b_reg1[half].z);
            __half2 p3 = __floats2half2_rn(b_reg0[half].w, b_reg1[half].w);
            Bs[k2][bcg + 0] = *(uint32_t*)&p0;
            Bs[k2][bcg + 1] = *(uint32_t*)&p1;
            Bs[k2][bcg + 2] = *(uint32_t*)&p2;
            Bs[k2][bcg + 3] = *(uint32_t*)&p3;
        }
    };

    fetch_tile(0);
    for (int k0 = 0; k0 < K; k0 += BK) {
        store_tile();
        __syncthreads();
        if (k0 + BK < K) fetch_tile(k0 + BK);   // loads overlap with mma below

#pragma unroll
        for (int kk = 0; kk < 2; kk++) {
            uint32_t bf[4][2];
#pragma unroll
            for (int nf = 0; nf < 4; nf++) {
                int col = warp_n * 32 + nf * 8 + (lane >> 2);
                bf[nf][0] = Bs[kk * 8 + (lane & 3)][col];
                bf[nf][1] = Bs[kk * 8 + 4 + (lane & 3)][col];
            }
#pragma unroll
            for (int mf = 0; mf < 4; mf++) {
                int row = warp_m * 64 + mf * 16 + (lane >> 2);
                uint32_t a0 = As[row][kk * 8 + (lane & 3)];
                uint32_t a1 = As[row + 8][kk * 8 + (lane & 3)];
                uint32_t a2 = As[row][kk * 8 + 4 + (lane & 3)];
                uint32_t a3 = As[row + 8][kk * 8 + 4 + (lane & 3)];
#pragma unroll
                for (int nf = 0; nf < 4; nf++)
                    mma_f16(acc[mf][nf], a0, a1, a2, a3, bf[nf][0], bf[nf][1]);
            }
        }
        __syncthreads();
    }

#pragma unroll
    for (int mf = 0; mf < 4; mf++) {
        int r0 = bm + warp_m * 64 + mf * 16 + (lane >> 2);
        int r1 = r0 + 8;
        float d0 = (r0 < M) ? g_dinv[r0] : 0.f;
        float d1 = (r1 < M) ? g_dinv[r1] : 0.f;
#pragma unroll
        for (int nf = 0; nf < 4; nf++) {
            int cn = bn + warp_n * 32 + nf * 8 + (lane & 3) * 2;
            if (r0 < M) {
                __half2 h = __floats2half2_rn(acc[mf][nf][0] * d0, acc[mf][nf][1] * d0);
                *(__half2*)&C[(size_t)r0 * N + cn] = h;
            }
            if (r1 < M) {
                __half2 h = __floats2half2_rn(acc[mf][nf][2] * d1, acc[mf][nf][3] * d1);
                *(__half2*)&C[(size_t)r1 * N + cn] = h;
            }
        }
    }
}

// ---------------- SpMM aggregation over fp16 tables: one warp per dst row ----
// out[i] = act( dinv[i] * (sum_{src in N(i)} hp[src] + hp[i]) + bias )
// MODE 0: hp = g_hp1h (256 cols), out = g_h2h (fp16), relu.
// MODE 1: hp = g_hp2h (128 cols), out = arg (fp32).
template <int VEC, bool RELU, int MODE>
__global__ __launch_bounds__(256) void spmm_kernel(
    const float* __restrict__ bias, float* __restrict__ outarg)
{
    const uint32_t* __restrict__ hp =
        (const uint32_t*)((MODE == 0) ? (const __half*)g_hp1h : (const __half*)g_hp2h);

    const int ncol32 = VEC * 32;
    int warp = (blockIdx.x * blockDim.x + threadIdx.x) >> 5;
    int lane = threadIdx.x & 31;
    if (warp >= N_NODES) return;
    int i = warp;

    float acc[VEC * 2];
    {
        uint32_t v[VEC];
        const uint32_t* p = hp + (size_t)i * ncol32 + lane * VEC;
        if (VEC == 4) { uint4 u = *(const uint4*)p; v[0]=u.x; v[1]=u.y; v[2]=u.z; v[3]=u.w; }
        else          { uint2 u = *(const uint2*)p; v[0]=u.x; v[1]=u.y; }
#pragma unroll
        for (int c = 0; c < VEC; c++) {
            float2 f = __half22float2(*(__half2*)&v[c]);
            acc[2*c] = f.x; acc[2*c+1] = f.y;
        }
    }

    int e = g_row_ptr[i];
    int end = g_row_ptr[i + 1];

    // 8-edge unroll: 8 row-gathers in flight per lane
    for (; e + 7 < end; e += 8) {
        int s[8];
#pragma unroll
        for (int j = 0; j < 8; j++) s[j] = g_csr_src[e + j];
        uint32_t v[8][VEC];
#pragma unroll
        for (int j = 0; j < 8; j++) {
            const uint32_t* p = hp + (size_t)s[j] * ncol32 + lane * VEC;
            if (VEC == 4) { uint4 u = *(const uint4*)p; v[j][0]=u.x; v[j][1]=u.y; v[j][2]=u.z; v[j][3]=u.w; }
            else          { uint2 u = *(const uint2*)p; v[j][0]=u.x; v[j][1]=u.y; }
        }
#pragma unroll
        for (int c = 0; c < VEC; c++) {
            float ax = 0.f, ay = 0.f;
#pragma unroll
            for (int j = 0; j < 8; j++) {
                float2 f = __half22float2(*(__half2*)&v[j][c]);
                ax += f.x; ay += f.y;
            }
            acc[2*c] += ax; acc[2*c+1] += ay;
        }
    }
    for (; e + 3 < end; e += 4) {
        int s[4];
#pragma unroll
        for (int j = 0; j < 4; j++) s[j] = g_csr_src[e + j];
        uint32_t v[4][VEC];
#pragma unroll
        for (int j = 0; j < 4; j++) {
            const uint32_t* p = hp + (size_t)s[j] * ncol32 + lane * VEC;
            if (VEC == 4) { uint4 u = *(const uint4*)p; v[j][0]=u.x; v[j][1]=u.y; v[j][2]=u.z; v[j][3]=u.w; }
            else          { uint2 u = *(const uint2*)p; v[j][0]=u.x; v[j][1]=u.y; }
        }
#pragma unroll
        for (int c = 0; c < VEC; c++) {
            float ax = 0.f, ay = 0.f;
#pragma unroll
            for (int j = 0; j < 4; j++) {
                float2 f = __half22float2(*(__half2*)&v[j][c]);
                ax += f.x; ay += f.y;
            }
            acc[2*c] += ax; acc[2*c+1] += ay;
        }
    }
    for (; e < end; e++) {
        int s0 = g_csr_src[e];
        uint32_t v[VEC];
        const uint32_t* p = hp + (size_t)s0 * ncol32 + lane * VEC;
        if (VEC == 4) { uint4 u = *(const uint4*)p; v[0]=u.x; v[1]=u.y; v[2]=u.z; v[3]=u.w; }
        else          { uint2 u = *(const uint2*)p; v[0]=u.x; v[1]=u.y; }
#pragma unroll
        for (int c = 0; c < VEC; c++) {
            float2 f = __half22float2(*(__half2*)&v[c]);
            acc[2*c] += f.x; acc[2*c+1] += f.y;
        }
    }

    float di = g_dinv[i];
    const float* bp = bias + lane * VEC * 2;
    float r[VEC * 2];
#pragma unroll
    for (int c = 0; c < VEC * 2; c += 4) {
        float4 bv = *(const float4*)&bp[c];
        r[c + 0] = fmaf(di, acc[c + 0], bv.x);
        r[c + 1] = fmaf(di, acc[c + 1], bv.y);
        r[c + 2] = fmaf(di, acc[c + 2], bv.z);
        r[c + 3] = fmaf(di, acc[c + 3], bv.w);
        if (RELU) {
            r[c + 0] = fmaxf(r[c + 0], 0.f); r[c + 1] = fmaxf(r[c + 1], 0.f);
            r[c + 2] = fmaxf(r[c + 2], 0.f); r[c + 3] = fmaxf(r[c + 3], 0.f);
        }
    }

    if (MODE == 0) {
        uint32_t* op = (uint32_t*)g_h2h + (size_t)i * ncol32 + lane * VEC;
        uint32_t w[VEC];
#pragma unroll
        for (int c = 0; c < VEC; c++) {
            __half2 h = __floats2half2_rn(r[2*c], r[2*c+1]);
            w[c] = *(uint32_t*)&h;
        }
        if (VEC == 4) *(uint4*)op = make_uint4(w[0], w[1], w[2], w[3]);
        else          *(uint2*)op = make_uint2(w[0], w[1]);
    } else {
        float* op = outarg + (size_t)i * ncol32 * 2 + lane * VEC * 2;
#pragma unroll
        for (int c = 0; c < VEC * 2; c += 4)
            *(float4*)&op[c] = make_float4(r[c], r[c+1], r[c+2], r[c+3]);
    }
}

// ---------------- launch ----------------
extern "C" void kernel_launch(void* const* d_in, const int* in_sizes, int n_in,
                              void* d_out, int out_size) {
    const float* x  = (const float*)d_in[0];
    const int*   ei = (const int*)d_in[1];
    const float* W1 = (const float*)d_in[2];
    const float* b1 = (const float*)d_in[3];
    const float* W2 = (const float*)d_in[4];
    const float* b2 = (const float*)d_in[5];
    float* out = (float*)d_out;

    const int T = 256;
    int nb_nodes = (N_NODES + T - 1) / T;
    int nb_edges2 = (N_EDGES / 2 + T - 1) / T;

    cudaStream_t s2;
    cudaEvent_t ev_deg, ev_csr, ev_zero;
    cudaStreamCreateWithFlags(&s2, cudaStreamNonBlocking);
    cudaEventCreateWithFlags(&ev_deg, cudaEventDisableTiming);
    cudaEventCreateWithFlags(&ev_csr, cudaEventDisableTiming);
    cudaEventCreateWithFlags(&ev_zero, cudaEventDisableTiming);

    // main stream: degree + dinv (deg is zero on entry; no init kernel)
    count_deg_kernel<<<nb_edges2, T>>>(ei);
    dinv_kernel<<<nb_nodes, T>>>();
    cudaEventRecord(ev_deg, 0);

    // side stream (forked via ev_deg): scan + CSR build, then restore deg==0
    cudaStreamWaitEvent(s2, ev_deg, 0);
    scan_partial_kernel<<<SCAN_NB, SCAN_T, 0, s2>>>();
    scan_blocksums_kernel<<<1, 1024, 0, s2>>>();
    scan_scatter_kernel<<<SCAN_NB, SCAN_T, 0, s2>>>();
    build_csr_kernel<<<nb_edges2, T, 0, s2>>>(ei);
    cudaEventRecord(ev_csr, s2);
    zero_deg_kernel<<<nb_nodes, T, 0, s2>>>();
    cudaEventRecord(ev_zero, s2);

    // main stream: GEMM1 in parallel with CSR build (needs only dinv)
    {
        dim3 grid((N_NODES + 127) / 128, HID / 128);
        gemm_f16_kernel<0><<<grid, 256>>>(x, W1, N_NODES, IN_CH, HID);
    }

    // join: SpMM1 needs CSR + hp1h
    cudaStreamWaitEvent(0, ev_csr, 0);
    {
        int blocks = (N_NODES * 32 + T - 1) / T;
        spmm_kernel<4, true, 0><<<blocks, T>>>(b1, nullptr);
    }
    {
        dim3 grid((N_NODES + 127) / 128, OUTC / 128);
        gemm_f16_kernel<1><<<grid, 256>>>(nullptr, W2, N_NODES, HID, OUTC);
    }
    {
        int blocks = (N_NODES * 32 + T - 1) / T;
        spmm_kernel<2, false, 1><<<blocks, T>>>(b2, out);
    }
    // join side-stream cleanup back into the capture stream before return
    cudaStreamWaitEvent(0, ev_zero, 0);
}

// round 13
// speedup vs baseline: 1.1443x; 1.0055x over previous
#include <cuda_runtime.h>
#include <cuda_fp16.h>
#include <cstdint>

// Problem constants (GAE_90589450207433)
#define N_NODES 100000
#define N_EDGES 3200000
#define IN_CH   256
#define HID     256
#define OUTC    128

#define SCAN_T    256
#define SCAN_NB   ((N_NODES + SCAN_T - 1) / SCAN_T)

#define CHUNK_A   50048                 // 391*128; SpMM1/GEMM2 pipeline split
#define CHUNK_B   (N_NODES - CHUNK_A)

// ---------------- device scratch (no allocs allowed) ----------------
// INVARIANT: g_deg is all-zero at kernel_launch entry (zero-init at load,
// re-zeroed at the end of every launch). deg counts EDGES only; self loop
// is accounted for via (deg+1) in dinv.
__device__ int   g_deg[N_NODES];
__device__ int   g_row_ptr[N_NODES + 1];
__device__ int   g_cursor[N_NODES];
__device__ float g_dinv[N_NODES];
__device__ int   g_csr_src[N_EDGES];
__device__ int   g_block_sums[SCAN_NB];
__device__ int   g_block_offs[SCAN_NB];
__device__ __align__(16) __half g_hp1h[(size_t)N_NODES * HID];   // fp16 dinv*(x W1)
__device__ __align__(16) __half g_hp2h[(size_t)N_NODES * OUTC];  // fp16 dinv*(h2 W2)
__device__ __align__(16) __half g_h2h[(size_t)N_NODES * HID];    // relu(layer1 out), fp16

// ---------------- degree / norm ----------------
__global__ void count_deg_kernel(const int* __restrict__ edge_index) {
    int t = blockIdx.x * blockDim.x + threadIdx.x;
    int e = t * 2;
    if (e + 1 < N_EDGES) {
        int2 d = *(const int2*)&edge_index[N_EDGES + e];
        if (d.x >= 0 && d.x < N_NODES) atomicAdd(&g_deg[d.x], 1);
        if (d.y >= 0 && d.y < N_NODES) atomicAdd(&g_deg[d.y], 1);
    } else if (e < N_EDGES) {
        int d = edge_index[N_EDGES + e];
        if (d >= 0 && d < N_NODES) atomicAdd(&g_deg[d], 1);
    }
}

__global__ void dinv_kernel() {
    int i = blockIdx.x * blockDim.x + threadIdx.x;
    if (i < N_NODES) g_dinv[i] = rsqrtf((float)(g_deg[i] + 1));  // +1 = self loop
}

__global__ void zero_deg_kernel() {
    int i = blockIdx.x * blockDim.x + threadIdx.x;
    if (i < N_NODES) g_deg[i] = 0;   // restore entry invariant for next replay
}

// ---------------- 3-phase multi-block exclusive scan of deg ----------------
__global__ __launch_bounds__(SCAN_T) void scan_partial_kernel() {
    __shared__ int warp_sums[SCAN_T / 32];
    int i = blockIdx.x * SCAN_T + threadIdx.x;
    int v = (i < N_NODES) ? g_deg[i] : 0;
    int s = v;
#pragma unroll
    for (int off = 16; off > 0; off >>= 1) s += __shfl_down_sync(0xffffffffu, s, off);
    int lane = threadIdx.x & 31;
    int wid  = threadIdx.x >> 5;
    if (lane == 0) warp_sums[wid] = s;
    __syncthreads();
    if (wid == 0) {
        int t = (lane < SCAN_T / 32) ? warp_sums[lane] : 0;
#pragma unroll
        for (int off = 16; off > 0; off >>= 1) t += __shfl_down_sync(0xffffffffu, t, off);
        if (lane == 0) g_block_sums[blockIdx.x] = t;
    }
}

__global__ __launch_bounds__(1024) void scan_blocksums_kernel() {
    __shared__ int sh[1024];
    int tid = threadIdx.x;
    int v = (tid < SCAN_NB) ? g_block_sums[tid] : 0;
    sh[tid] = v;
    __syncthreads();
    for (int off = 1; off < 1024; off <<= 1) {
        int t = (tid >= off) ? sh[tid - off] : 0;
        __syncthreads();
        sh[tid] += t;
        __syncthreads();
    }
    if (tid < SCAN_NB) g_block_offs[tid] = sh[tid] - v;
    if (tid == 0) g_row_ptr[N_NODES] = N_EDGES;
}

__global__ __launch_bounds__(SCAN_T) void scan_scatter_kernel() {
    __shared__ int warp_incl[SCAN_T / 32];
    int i = blockIdx.x * SCAN_T + threadIdx.x;
    int v = (i < N_NODES) ? g_deg[i] : 0;
    int lane = threadIdx.x & 31;
    int wid  = threadIdx.x >> 5;
    int incl = v;
#pragma unroll
    for (int off = 1; off < 32; off <<= 1) {
        int t = __shfl_up_sync(0xffffffffu, incl, off);
        if (lane >= off) incl += t;
    }
    if (lane == 31) warp_incl[wid] = incl;
    __syncthreads();
    if (wid == 0) {
        int t = (lane < SCAN_T / 32) ? warp_incl[lane] : 0;
#pragma unroll
        for (int off = 1; off < SCAN_T / 32; off <<= 1) {
            int u = __shfl_up_sync(0xffffffffu, t, off);
            if (lane >= off) t += u;
        }
        if (lane < SCAN_T / 32) warp_incl[lane] = t;
    }
    __syncthreads();
    int warp_off = (wid == 0) ? 0 : warp_incl[wid - 1];
    int excl = g_block_offs[blockIdx.x] + warp_off + (incl - v);
    if (i < N_NODES) {
        g_row_ptr[i] = excl;
        g_cursor[i]  = excl;
    }
}

__global__ void build_csr_kernel(const int* __restrict__ edge_index) {
    int t = blockIdx.x * blockDim.x + threadIdx.x;
    int e = t * 2;
    if (e + 1 < N_EDGES) {
        int2 s = *(const int2*)&edge_index[e];
        int2 d = *(const int2*)&edge_index[N_EDGES + e];
        if (d.x >= 0 && d.x < N_NODES && s.x >= 0 && s.x < N_NODES) {
            int pos = atomicAdd(&g_cursor[d.x], 1);
            g_csr_src[pos] = s.x;
        }
        if (d.y >= 0 && d.y < N_NODES && s.y >= 0 && s.y < N_NODES) {
            int pos = atomicAdd(&g_cursor[d.y], 1);
            g_csr_src[pos] = s.y;
        }
    } else if (e < N_EDGES) {
        int s = edge_index[e];
        int d = edge_index[N_EDGES + e];
        if (d >= 0 && d < N_NODES && s >= 0 && s < N_NODES) {
            int pos = atomicAdd(&g_cursor[d], 1);
            g_csr_src[pos] = s;
        }
    }
}

// ---------------- FP16 tensor-core GEMM (software-pipelined) ----------------
// Ch[row] = fp16(dinv[row] * (A@B)[row]); rows [row0, row0+rows)
__device__ __forceinline__ void mma_f16(float* c, uint32_t a0, uint32_t a1,
                                        uint32_t a2, uint32_t a3,
                                        uint32_t b0, uint32_t b1) {
    asm volatile(
        "mma.sync.aligned.m16n8k16.row.col.f32.f16.f16.f32 "
        "{%0,%1,%2,%3}, {%4,%5,%6,%7}, {%8,%9}, {%0,%1,%2,%3};"
        : "+f"(c[0]), "+f"(c[1]), "+f"(c[2]), "+f"(c[3])
        : "r"(a0), "r"(a1), "r"(a2), "r"(a3), "r"(b0), "r"(b1));
}

#define APAD 4
#define BPAD 8
template <int MODE>
__global__ __launch_bounds__(256) void gemm_f16_kernel(
    const float* __restrict__ Aarg, const float* __restrict__ B,
    int row0, int rows, int K, int N)
{
    __half* __restrict__ C = (MODE == 0) ? g_hp1h : g_hp2h;
    const int Mend = row0 + rows;

    const int BM = 128, BN = 128, BK = 32;   // BK in halves
    __shared__ uint32_t As[BM][BK / 2 + APAD];
    __shared__ uint32_t Bs[BK / 2][BN + BPAD];

    int bm = row0 + blockIdx.x * BM;
    int bn = blockIdx.y * BN;
    int tid = threadIdx.x;
    int lane = tid & 31;
    int wid  = tid >> 5;
    int warp_m = wid & 1;
    int warp_n = wid >> 1;

    float acc[4][4][4];
#pragma unroll
    for (int mf = 0; mf < 4; mf++)
#pragma unroll
        for (int nf = 0; nf < 4; nf++)
#pragma unroll
            for (int c = 0; c < 4; c++) acc[mf][nf][c] = 0.f;

    int ar  = tid >> 3;
    int ac4 = (tid & 7) * 4;
    int bk2 = tid >> 5;
    int bcg = (tid & 31) * 4;

    uint2  a_reg[4];
    float4 b_reg0[2], b_reg1[2];

    auto fetch_tile = [&](int k0) {
#pragma unroll
        for (int rr = 0; rr < 4; rr++) {
            int row = bm + ar + rr * 32;
            if (MODE == 0) {
                float4 v = make_float4(0.f, 0.f, 0.f, 0.f);
                if (row < Mend) v = *(const float4*)&Aarg[(size_t)row * K + k0 + ac4];
                __half2 h01 = __floats2half2_rn(v.x, v.y);
                __half2 h23 = __floats2half2_rn(v.z, v.w);
                a_reg[rr].x = *(uint32_t*)&h01;
                a_reg[rr].y = *(uint32_t*)&h23;
            } else {
                uint2 v = make_uint2(0u, 0u);
                if (row < Mend) v = *(const uint2*)&g_h2h[(size_t)row * K + k0 + ac4];
                a_reg[rr] = v;
            }
        }
#pragma unroll
        for (int half = 0; half < 2; half++) {
            int k2 = bk2 + half * 8;
            int gk = k0 + 2 * k2;
            b_reg0[half] = *(const float4*)&B[(size_t)gk * N + bn + bcg];
            b_reg1[half] = *(const float4*)&B[(size_t)(gk + 1) * N + bn + bcg];
        }
    };
    auto store_tile = [&]() {
#pragma unroll
        for (int rr = 0; rr < 4; rr++) {
            As[ar + rr * 32][ac4 / 2]     = a_reg[rr].x;
            As[ar + rr * 32][ac4 / 2 + 1] = a_reg[rr].y;
        }
#pragma unroll
        for (int half = 0; half < 2; half++) {
            int k2 = bk2 + half * 8;
            __half2 p0 = __floats2half2_rn(b_reg0[half].x, b_reg1[half].x);
            __half2 p1 = __floats2half2_rn(b_reg0[half].y, b_reg1[half].y);
            __half2 p2 = __floats2half2_rn(b_reg0[half].z, b_reg1[half].z);
            __half2 p3 = __floats2half2_rn(b_reg0[half].w, b_reg1[half].w);
            Bs[k2][bcg + 0] = *(uint32_t*)&p0;
            Bs[k2][bcg + 1] = *(uint32_t*)&p1;
            Bs[k2][bcg + 2] = *(uint32_t*)&p2;
            Bs[k2][bcg + 3] = *(uint32_t*)&p3;
        }
    };

    fetch_tile(0);
    for (int k0 = 0; k0 < K; k0 += BK) {
        store_tile();
        __syncthreads();
        if (k0 + BK < K) fetch_tile(k0 + BK);

#pragma unroll
        for (int kk = 0; kk < 2; kk++) {
            uint32_t bf[4][2];
#pragma unroll
            for (int nf = 0; nf < 4; nf++) {
                int col = warp_n * 32 + nf * 8 + (lane >> 2);
                bf[nf][0] = Bs[kk * 8 + (lane & 3)][col];
                bf[nf][1] = Bs[kk * 8 + 4 + (lane & 3)][col];
            }
#pragma unroll
            for (int mf = 0; mf < 4; mf++) {
                int row = warp_m * 64 + mf * 16 + (lane >> 2);
                uint32_t a0 = As[row][kk * 8 + (lane & 3)];
                uint32_t a1 = As[row + 8][kk * 8 + (lane & 3)];
                uint32_t a2 = As[row][kk * 8 + 4 + (lane & 3)];
                uint32_t a3 = As[row + 8][kk * 8 + 4 + (lane & 3)];
#pragma unroll
                for (int nf = 0; nf < 4; nf++)
                    mma_f16(acc[mf][nf], a0, a1, a2, a3, bf[nf][0], bf[nf][1]);
            }
        }
        __syncthreads();
    }

#pragma unroll
    for (int mf = 0; mf < 4; mf++) {
        int r0 = bm + warp_m * 64 + mf * 16 + (lane >> 2);
        int r1 = r0 + 8;
        float d0 = (r0 < Mend) ? g_dinv[r0] : 0.f;
        float d1 = (r1 < Mend) ? g_dinv[r1] : 0.f;
#pragma unroll
        for (int nf = 0; nf < 4; nf++) {
            int cn = bn + warp_n * 32 + nf * 8 + (lane & 3) * 2;
            if (r0 < Mend) {
                __half2 h = __floats2half2_rn(acc[mf][nf][0] * d0, acc[mf][nf][1] * d0);
                *(__half2*)&C[(size_t)r0 * N + cn] = h;
            }
            if (r1 < Mend) {
                __half2 h = __floats2half2_rn(acc[mf][nf][2] * d1, acc[mf][nf][3] * d1);
                *(__half2*)&C[(size_t)r1 * N + cn] = h;
            }
        }
    }
}

// ---------------- SpMM aggregation over fp16 tables: one warp per dst row ----
// out[i] = act( dinv[i] * (sum_{src in N(i)} hp[src] + hp[i]) + bias )
// MODE 0: hp = g_hp1h (256 cols), out = g_h2h (fp16), relu.  Rows [row0,row0+rows).
// MODE 1: hp = g_hp2h (128 cols), out = arg (fp32).
template <int VEC, bool RELU, int MODE>
__global__ __launch_bounds__(256) void spmm_kernel(
    const float* __restrict__ bias, float* __restrict__ outarg,
    int row0, int rows)
{
    const uint32_t* __restrict__ hp =
        (const uint32_t*)((MODE == 0) ? (const __half*)g_hp1h : (const __half*)g_hp2h);

    const int ncol32 = VEC * 32;
    int warp = (blockIdx.x * blockDim.x + threadIdx.x) >> 5;
    int lane = threadIdx.x & 31;
    if (warp >= rows) return;
    int i = row0 + warp;

    float acc[VEC * 2];
    {
        uint32_t v[VEC];
        const uint32_t* p = hp + (size_t)i * ncol32 + lane * VEC;
        if (VEC == 4) { uint4 u = *(const uint4*)p; v[0]=u.x; v[1]=u.y; v[2]=u.z; v[3]=u.w; }
        else          { uint2 u = *(const uint2*)p; v[0]=u.x; v[1]=u.y; }
#pragma unroll
        for (int c = 0; c < VEC; c++) {
            float2 f = __half22float2(*(__half2*)&v[c]);
            acc[2*c] = f.x; acc[2*c+1] = f.y;
        }
    }

    int e = g_row_ptr[i];
    int end = g_row_ptr[i + 1];

    // 8-edge unroll: 8 row-gathers in flight per lane
    for (; e + 7 < end; e += 8) {
        int s[8];
#pragma unroll
        for (int j = 0; j < 8; j++) s[j] = g_csr_src[e + j];
        uint32_t v[8][VEC];
#pragma unroll
        for (int j = 0; j < 8; j++) {
            const uint32_t* p = hp + (size_t)s[j] * ncol32 + lane * VEC;
            if (VEC == 4) { uint4 u = *(const uint4*)p; v[j][0]=u.x; v[j][1]=u.y; v[j][2]=u.z; v[j][3]=u.w; }
            else          { uint2 u = *(const uint2*)p; v[j][0]=u.x; v[j][1]=u.y; }
        }
#pragma unroll
        for (int c = 0; c < VEC; c++) {
            float ax = 0.f, ay = 0.f;
#pragma unroll
            for (int j = 0; j < 8; j++) {
                float2 f = __half22float2(*(__half2*)&v[j][c]);
                ax += f.x; ay += f.y;
            }
            acc[2*c] += ax; acc[2*c+1] += ay;
        }
    }
    for (; e + 3 < end; e += 4) {
        int s[4];
#pragma unroll
        for (int j = 0; j < 4; j++) s[j] = g_csr_src[e + j];
        uint32_t v[4][VEC];
#pragma unroll
        for (int j = 0; j < 4; j++) {
            const uint32_t* p = hp + (size_t)s[j] * ncol32 + lane * VEC;
            if (VEC == 4) { uint4 u = *(const uint4*)p; v[j][0]=u.x; v[j][1]=u.y; v[j][2]=u.z; v[j][3]=u.w; }
            else          { uint2 u = *(const uint2*)p; v[j][0]=u.x; v[j][1]=u.y; }
        }
#pragma unroll
        for (int c = 0; c < VEC; c++) {
            float ax = 0.f, ay = 0.f;
#pragma unroll
            for (int j = 0; j < 4; j++) {
                float2 f = __half22float2(*(__half2*)&v[j][c]);
                ax += f.x; ay += f.y;
            }
            acc[2*c] += ax; acc[2*c+1] += ay;
        }
    }
    for (; e < end; e++) {
        int s0 = g_csr_src[e];
        uint32_t v[VEC];
        const uint32_t* p = hp + (size_t)s0 * ncol32 + lane * VEC;
        if (VEC == 4) { uint4 u = *(const uint4*)p; v[0]=u.x; v[1]=u.y; v[2]=u.z; v[3]=u.w; }
        else          { uint2 u = *(const uint2*)p; v[0]=u.x; v[1]=u.y; }
#pragma unroll
        for (int c = 0; c < VEC; c++) {
            float2 f = __half22float2(*(__half2*)&v[c]);
            acc[2*c] += f.x; acc[2*c+1] += f.y;
        }
    }

    float di = g_dinv[i];
    const float* bp = bias + lane * VEC * 2;
    float r[VEC * 2];
#pragma unroll
    for (int c = 0; c < VEC * 2; c += 4) {
        float4 bv = *(const float4*)&bp[c];
        r[c + 0] = fmaf(di, acc[c + 0], bv.x);
        r[c + 1] = fmaf(di, acc[c + 1], bv.y);
        r[c + 2] = fmaf(di, acc[c + 2], bv.z);
        r[c + 3] = fmaf(di, acc[c + 3], bv.w);
        if (RELU) {
            r[c + 0] = fmaxf(r[c + 0], 0.f); r[c + 1] = fmaxf(r[c + 1], 0.f);
            r[c + 2] = fmaxf(r[c + 2], 0.f); r[c + 3] = fmaxf(r[c + 3], 0.f);
        }
    }

    if (MODE == 0) {
        uint32_t* op = (uint32_t*)g_h2h + (size_t)i * ncol32 + lane * VEC;
        uint32_t w[VEC];
#pragma unroll
        for (int c = 0; c < VEC; c++) {
            __half2 h = __floats2half2_rn(r[2*c], r[2*c+1]);
            w[c] = *(uint32_t*)&h;
        }
        if (VEC == 4) *(uint4*)op = make_uint4(w[0], w[1], w[2], w[3]);
        else          *(uint2*)op = make_uint2(w[0], w[1]);
    } else {
        float* op = outarg + (size_t)i * ncol32 * 2 + lane * VEC * 2;
#pragma unroll
        for (int c = 0; c < VEC * 2; c += 4)
            *(float4*)&op[c] = make_float4(r[c], r[c+1], r[c+2], r[c+3]);
    }
}

// ---------------- launch ----------------
extern "C" void kernel_launch(void* const* d_in, const int* in_sizes, int n_in,
                              void* d_out, int out_size) {
    const float* x  = (const float*)d_in[0];
    const int*   ei = (const int*)d_in[1];
    const float* W1 = (const float*)d_in[2];
    const float* b1 = (const float*)d_in[3];
    const float* W2 = (const float*)d_in[4];
    const float* b2 = (const float*)d_in[5];
    float* out = (float*)d_out;

    const int T = 256;
    int nb_nodes = (N_NODES + T - 1) / T;
    int nb_edges2 = (N_EDGES / 2 + T - 1) / T;

    cudaStream_t s2;
    cudaEvent_t ev_deg, ev_csr, ev_zero, ev_s1a, ev_g2a;
    cudaStreamCreateWithFlags(&s2, cudaStreamNonBlocking);
    cudaEventCreateWithFlags(&ev_deg, cudaEventDisableTiming);
    cudaEventCreateWithFlags(&ev_csr, cudaEventDisableTiming);
    cudaEventCreateWithFlags(&ev_zero, cudaEventDisableTiming);
    cudaEventCreateWithFlags(&ev_s1a, cudaEventDisableTiming);
    cudaEventCreateWithFlags(&ev_g2a, cudaEventDisableTiming);

    // main stream: degree + dinv (deg is zero on entry; no init kernel)
    count_deg_kernel<<<nb_edges2, T>>>(ei);
    dinv_kernel<<<nb_nodes, T>>>();
    cudaEventRecord(ev_deg, 0);

    // side stream (forked via ev_deg): scan + CSR build, then restore deg==0
    cudaStreamWaitEvent(s2, ev_deg, 0);
    scan_partial_kernel<<<SCAN_NB, SCAN_T, 0, s2>>>();
    scan_blocksums_kernel<<<1, 1024, 0, s2>>>();
    scan_scatter_kernel<<<SCAN_NB, SCAN_T, 0, s2>>>();
    build_csr_kernel<<<nb_edges2, T, 0, s2>>>(ei);
    cudaEventRecord(ev_csr, s2);
    zero_deg_kernel<<<nb_nodes, T, 0, s2>>>();
    cudaEventRecord(ev_zero, s2);

    // main stream: GEMM1 in parallel with CSR build (needs only dinv)
    {
        dim3 grid((N_NODES + 127) / 128, HID / 128);
        gemm_f16_kernel<0><<<grid, 256>>>(x, W1, 0, N_NODES, IN_CH, HID);
    }

    // join: SpMM1 needs CSR + hp1h
    cudaStreamWaitEvent(0, ev_csr, 0);

    // ---- pipeline: SpMM1(A) -> [GEMM2(A) on s2 || SpMM1(B)] -> GEMM2(B) ----
    {
        int blocks = (CHUNK_A * 32 + T - 1) / T;
        spmm_kernel<4, true, 0><<<blocks, T>>>(b1, nullptr, 0, CHUNK_A);
    }
    cudaEventRecord(ev_s1a, 0);

    cudaStreamWaitEvent(s2, ev_s1a, 0);
    {
        dim3 grid((CHUNK_A + 127) / 128, OUTC / 128);
        gemm_f16_kernel<1><<<grid, 256, 0, s2>>>(nullptr, W2, 0, CHUNK_A, HID, OUTC);
    }
    cudaEventRecord(ev_g2a, s2);

    {
        int blocks = (CHUNK_B * 32 + T - 1) / T;
        spmm_kernel<4, true, 0><<<blocks, T>>>(b1, nullptr, CHUNK_A, CHUNK_B);
    }
    {
        dim3 grid((CHUNK_B + 127) / 128, OUTC / 128);
        gemm_f16_kernel<1><<<grid, 256>>>(nullptr, W2, CHUNK_A, CHUNK_B, HID, OUTC);
    }
    cudaStreamWaitEvent(0, ev_g2a, 0);

    // ---- final aggregation -> out ----
    {
        int blocks = (N_NODES * 32 + T - 1) / T;
        spmm_kernel<2, false, 1><<<blocks, T>>>(b2, out, 0, N_NODES);
    }
    // join side-stream cleanup back into the capture stream before return
    cudaStreamWaitEvent(0, ev_zero, 0);
}